// round 1
// baseline (speedup 1.0000x reference)
#include <cuda_runtime.h>
#include <cstdint>

// Problem constants
#define Bn    16
#define NCn   80
#define An    33600
#define PRE   750
#define POST  30
#define CH    256

// Output layout (flattened tuple): cls_f, reg_f, box_f, sc_f
#define OUT_CLS_OFF  0
#define OUT_REG_OFF  (Bn*POST*CH)                 // 122880
#define OUT_BOX_OFF  (2*Bn*POST*CH)               // 245760
#define OUT_SC_OFF   (2*Bn*POST*CH + Bn*POST*4)   // 247680

// Device scratch (no allocations allowed)
__device__ float g_maxs[Bn * An];
__device__ int   g_cls[Bn * An];
__device__ int   g_final[Bn * POST];

// ---------------------------------------------------------------------------
// K1: per-anchor max score + argmax (first occurrence) over 80 classes.
// float4 vectorized: each thread handles 4 consecutive anchors.
// ---------------------------------------------------------------------------
__global__ void k_maxscore(const float* __restrict__ raw) {
    const int QA = An / 4;                    // 8400
    int t = blockIdx.x * blockDim.x + threadIdx.x;
    if (t >= Bn * QA) return;
    int b = t / QA;
    int q = t - b * QA;

    const float* base = raw + (size_t)b * 84 * An + (size_t)4 * An;  // class 0 row

    float4 best = __ldg(((const float4*)base) + q);
    int4 bi = make_int4(0, 0, 0, 0);
#pragma unroll 4
    for (int c = 1; c < NCn; ++c) {
        float4 v = __ldg(((const float4*)(base + (size_t)c * An)) + q);
        if (v.x > best.x) { best.x = v.x; bi.x = c; }
        if (v.y > best.y) { best.y = v.y; bi.y = c; }
        if (v.z > best.z) { best.z = v.z; bi.z = c; }
        if (v.w > best.w) { best.w = v.w; bi.w = c; }
    }
    ((float4*)g_maxs)[b * QA + q] = best;
    ((int4*)g_cls)[b * QA + q] = bi;
}

// ---------------------------------------------------------------------------
// K2: per-frame (one block of 1024 threads):
//   1. exact top-750 via 64-bit radix select (key = score_bits<<32 | ~index)
//   2. compaction + bitonic sort (descending) -> exact jax.lax.top_k order
//   3. class-offset NMS replicated in fp32 with early exit at 30 kept
//   4. write final 30 anchor indices
// ---------------------------------------------------------------------------
__global__ __launch_bounds__(1024) void k_select(const float* __restrict__ raw) {
    const int b = blockIdx.x;
    const int tid = threadIdx.x;
    const int T = 1024;

    __shared__ unsigned hist[256];
    __shared__ unsigned long long sh_prefix;
    __shared__ unsigned sh_k;
    __shared__ unsigned long long keys[1024];
    __shared__ float bx1[PRE], by1[PRE], bx2[PRE], by2[PRE], barea[PRE];
    __shared__ int bcls[PRE];
    __shared__ int keep[PRE];
    __shared__ int sh_cnt, sh_kept, sh_stop, sh_maxbits;

    const float* ms = g_maxs + (size_t)b * An;
    const int* cl = g_cls + (size_t)b * An;

    // ---- radix select: find exact 750th-largest 64-bit key ----
    unsigned long long prefix = 0ULL;
    unsigned kk = PRE;
    const int ITER = (An + T - 1) / T;  // 33

    for (int pass = 0; pass < 8; ++pass) {
        int shift = 56 - pass * 8;
        unsigned long long hi_mask = (pass == 0) ? 0ULL : (~0ULL << (unsigned)(shift + 8));

        for (int i = tid; i < 256; i += T) hist[i] = 0;
        __syncthreads();

        for (int it = 0; it < ITER; ++it) {
            int a = it * T + tid;
            unsigned d = 0xFFFFFFFFu;
            if (a < An) {
                unsigned long long key =
                    ((unsigned long long)__float_as_uint(ms[a]) << 32) | (unsigned)(~a);
                if ((key & hi_mask) == prefix)
                    d = (unsigned)(key >> shift) & 255u;
            }
            unsigned grp = __match_any_sync(0xFFFFFFFFu, d);
            if (d != 0xFFFFFFFFu) {
                int leader = __ffs(grp) - 1;
                if ((int)(tid & 31) == leader) atomicAdd(&hist[d], (unsigned)__popc(grp));
            }
        }
        __syncthreads();

        if (tid == 0) {
            unsigned cum = 0;
            int d = 255;
            for (; d >= 0; --d) {
                unsigned c = hist[d];
                if (cum + c >= kk) break;
                cum += c;
            }
            if (d < 0) d = 0;  // safety (cannot happen)
            prefix |= ((unsigned long long)d) << shift;
            kk -= cum;
            sh_prefix = prefix;
            sh_k = kk;
        }
        __syncthreads();
        prefix = sh_prefix;
        kk = sh_k;
        __syncthreads();
    }

    // ---- compaction: exactly 750 keys >= prefix (keys are unique) ----
    if (tid == 0) sh_cnt = 0;
    __syncthreads();
    for (int a = tid; a < An; a += T) {
        unsigned long long key =
            ((unsigned long long)__float_as_uint(ms[a]) << 32) | (unsigned)(~a);
        if (key >= prefix) {
            int pos = atomicAdd(&sh_cnt, 1);
            if (pos < 1024) keys[pos] = key;
        }
    }
    __syncthreads();
    int cnt = sh_cnt;
    for (int i = cnt + tid; i < 1024; i += T) keys[i] = 0ULL;
    __syncthreads();

    // ---- bitonic sort descending (1024 elements, 1 thread each) ----
    for (int k2 = 2; k2 <= 1024; k2 <<= 1) {
        for (int j = k2 >> 1; j > 0; j >>= 1) {
            int i = tid;
            int ixj = i ^ j;
            if (ixj > i) {
                unsigned long long x = keys[i], y = keys[ixj];
                bool desc = ((i & k2) == 0);
                if (desc ? (x < y) : (x > y)) { keys[i] = y; keys[ixj] = x; }
            }
            __syncthreads();
        }
    }

    // ---- load boxes / classes for the sorted 750; find max coordinate ----
    if (tid == 0) sh_maxbits = 0;
    __syncthreads();
    for (int i = tid; i < PRE; i += T) {
        int a = (int)(~(unsigned)(keys[i] & 0xFFFFFFFFULL));
        const float* rb = raw + (size_t)b * 84 * An;
        float x1 = rb[0 * (size_t)An + a];
        float y1 = rb[1 * (size_t)An + a];
        float x2 = rb[2 * (size_t)An + a];
        float y2 = rb[3 * (size_t)An + a];
        bx1[i] = x1; by1[i] = y1; bx2[i] = x2; by2[i] = y2;
        bcls[i] = cl[a];
        float m = fmaxf(fmaxf(x1, y1), fmaxf(x2, y2));
        atomicMax(&sh_maxbits, __float_as_int(m));  // coords >= 0: int-compare valid
        keep[i] = 1;
    }
    __syncthreads();

    float off_scale = __int_as_float(sh_maxbits) + 1.0f;
    for (int i = tid; i < PRE; i += T) {
        float off = (float)bcls[i] * off_scale;
        float x1 = bx1[i] + off, y1 = by1[i] + off;
        float x2 = bx2[i] + off, y2 = by2[i] + off;
        bx1[i] = x1; by1[i] = y1; bx2[i] = x2; by2[i] = y2;
        barea[i] = (x2 - x1) * (y2 - y1);
    }
    if (tid == 0) { sh_kept = 0; sh_stop = 0; }
    __syncthreads();

    // ---- sequential NMS (exact reference semantics), early exit at 30 kept ----
    for (int i = 0; i < PRE; ++i) {
        if (sh_stop) break;
        int ki = keep[i];
        if (ki) {
            float X1 = bx1[i], Y1 = by1[i], X2 = bx2[i], Y2 = by2[i], AR = barea[i];
            int CI = bcls[i];
            for (int j = i + 1 + tid; j < PRE; j += T) {
                if (keep[j] && bcls[j] == CI) {
                    float iw = fminf(X2, bx2[j]) - fmaxf(X1, bx1[j]);
                    iw = fmaxf(iw, 0.0f);
                    float ih = fminf(Y2, by2[j]) - fmaxf(Y1, by1[j]);
                    ih = fmaxf(ih, 0.0f);
                    float inter = iw * ih;
                    float iou = __fdiv_rn(inter, AR + barea[j] - inter);
                    if (iou > 0.4f) keep[j] = 0;
                }
            }
            if (tid == 0) {
                sh_kept++;
                if (sh_kept >= POST) sh_stop = 1;
            }
        }
        __syncthreads();
    }

    // ---- stable-partition: first 30 kept (in order), then unkept fill ----
    if (tid == 0) {
        int c2 = 0;
        for (int i = 0; i < PRE && c2 < POST; ++i)
            if (keep[i]) {
                g_final[b * POST + c2] = (int)(~(unsigned)(keys[i] & 0xFFFFFFFFULL));
                c2++;
            }
        for (int i = 0; i < PRE && c2 < POST; ++i)
            if (!keep[i]) {
                g_final[b * POST + c2] = (int)(~(unsigned)(keys[i] & 0xFFFFFFFFULL));
                c2++;
            }
    }
}

// ---------------------------------------------------------------------------
// K3: gather vid/reg features (256 each), boxes (4), scores (1) for the
// B*POST = 480 final selections into the concatenated output buffer.
// ---------------------------------------------------------------------------
__global__ void k_gather(const float* __restrict__ raw,
                         const float* __restrict__ vid,
                         const float* __restrict__ reg,
                         float* __restrict__ out) {
    int r = blockIdx.x;             // 0 .. B*POST-1
    int b = r / POST;
    int a = g_final[r];
    int t = threadIdx.x;

    size_t row = ((size_t)b * An + a) * CH;
    const float4* v = (const float4*)(vid + row);
    const float4* g = (const float4*)(reg + row);
    float4* oc = (float4*)(out + OUT_CLS_OFF + (size_t)r * CH);
    float4* og = (float4*)(out + OUT_REG_OFF + (size_t)r * CH);

    if (t < 64) oc[t] = __ldg(v + t);
    else        og[t - 64] = __ldg(g + (t - 64));

    if (t < 4)
        out[OUT_BOX_OFF + r * 4 + t] = raw[(size_t)b * 84 * An + (size_t)t * An + a];
    if (t == 4)
        out[OUT_SC_OFF + r] = g_maxs[(size_t)b * An + a];
}

// ---------------------------------------------------------------------------
extern "C" void kernel_launch(void* const* d_in, const int* in_sizes, int n_in,
                              void* d_out, int out_size) {
    const float* raw = (const float*)d_in[0];
    const float* vid = (const float*)d_in[1];
    const float* reg = (const float*)d_in[2];
    float* out = (float*)d_out;

    const int QA = An / 4;
    int threads1 = 256;
    int blocks1 = (Bn * QA + threads1 - 1) / threads1;
    k_maxscore<<<blocks1, threads1>>>(raw);
    k_select<<<Bn, 1024>>>(raw);
    k_gather<<<Bn * POST, 128>>>(raw, vid, reg, out);
}

// round 2
// speedup vs baseline: 1.6766x; 1.6766x over previous
#include <cuda_runtime.h>
#include <cstdint>

#define Bn    16
#define NCn   80
#define An    33600
#define QAn   (An/4)          /* 8400 */
#define PRE   750
#define POST  30
#define CH    256

#define OUT_CLS_OFF  0
#define OUT_REG_OFF  (Bn*POST*CH)
#define OUT_BOX_OFF  (2*Bn*POST*CH)
#define OUT_SC_OFF   (2*Bn*POST*CH + Bn*POST*4)

__device__ float g_maxs[Bn * An];
__device__ int   g_cls[Bn * An];
__device__ int   g_final[Bn * POST];

// ---------------------------------------------------------------------------
// K1: per-anchor max+argmax over 80 classes, split 2 ways across thread pairs
// (classes 0-39 on even lane, 40-79 on odd lane), combined via shfl.
// First-occurrence argmax semantics: strict > within half; ties across halves
// resolve to the low half (smaller class id).
// ---------------------------------------------------------------------------
__global__ void k_maxscore(const float* __restrict__ raw) {
    int t = blockIdx.x * blockDim.x + threadIdx.x;
    if (t >= Bn * QAn * 2) return;
    int half = t & 1;
    int pair = t >> 1;
    int b = pair / QAn;
    int q = pair - b * QAn;

    const float* base = raw + (size_t)b * 84 * An + (size_t)(4 + half * 40) * An;

    float4 best = __ldg((const float4*)base + q);
    int4 bi = make_int4(0, 0, 0, 0);
#pragma unroll 8
    for (int c = 1; c < 40; ++c) {
        float4 v = __ldg((const float4*)(base + (size_t)c * An) + q);
        if (v.x > best.x) { best.x = v.x; bi.x = c; }
        if (v.y > best.y) { best.y = v.y; bi.y = c; }
        if (v.z > best.z) { best.z = v.z; bi.z = c; }
        if (v.w > best.w) { best.w = v.w; bi.w = c; }
    }
    // exchange with partner lane
    float px = __shfl_xor_sync(0xFFFFFFFFu, best.x, 1);
    float py = __shfl_xor_sync(0xFFFFFFFFu, best.y, 1);
    float pz = __shfl_xor_sync(0xFFFFFFFFu, best.z, 1);
    float pw = __shfl_xor_sync(0xFFFFFFFFu, best.w, 1);
    int cx = __shfl_xor_sync(0xFFFFFFFFu, bi.x, 1);
    int cy = __shfl_xor_sync(0xFFFFFFFFu, bi.y, 1);
    int cz = __shfl_xor_sync(0xFFFFFFFFu, bi.z, 1);
    int cw = __shfl_xor_sync(0xFFFFFFFFu, bi.w, 1);

    if (half == 0) {
        if (px > best.x) { best.x = px; bi.x = cx + 40; }
        if (py > best.y) { best.y = py; bi.y = cy + 40; }
        if (pz > best.z) { best.z = pz; bi.z = cz + 40; }
        if (pw > best.w) { best.w = pw; bi.w = cw + 40; }
        ((float4*)g_maxs)[pair] = best;
        ((int4*)g_cls)[pair] = bi;
    }
}

// ---------------------------------------------------------------------------
// K2: per-frame top-750 + NMS + final 30 indices.
// Selection: one histogram pass over t = bits(1.0f - s) (strictly
// order-reversing in s), pivot bin, compact superset (definite + pivot bin),
// sort superset by TRUE key (score_bits<<32 | ~index) descending -> exact
// jax.lax.top_k order. Refinement levels on lower t bits if superset > 1024.
// ---------------------------------------------------------------------------
__global__ __launch_bounds__(1024) void k_select(const float* __restrict__ raw) {
    const int b = blockIdx.x;
    const int tid = threadIdx.x;
    const int T = 1024;

    __shared__ unsigned hist[2048];
    __shared__ unsigned coarse[64];
    __shared__ unsigned long long keys[1024];
    __shared__ float bx1[PRE], by1[PRE], bx2[PRE], by2[PRE], barea[PRE];
    __shared__ int bcls[PRE];
    __shared__ int keep[PRE];
    __shared__ int sh_pos, sh_maxbits;
    __shared__ int sh_th1, sh_th2, sh_th3, sh_lvl, sh_D, sh_cnt;

    const float* ms = g_maxs + (size_t)b * An;
    const int* cl = g_cls + (size_t)b * An;

    // ---- level-1 histogram: top 11 bits of t ----
    for (int i = tid; i < 2048; i += T) hist[i] = 0;
    __syncthreads();

    const int QI = (QAn + T - 1) / T;  // 9
    for (int it = 0; it < QI; ++it) {
        int q = it * T + tid;
        if (q < QAn) {
            float4 s = ((const float4*)ms)[q];
            unsigned v[4];
            v[0] = __float_as_uint(1.0f - s.x) >> 21;
            v[1] = __float_as_uint(1.0f - s.y) >> 21;
            v[2] = __float_as_uint(1.0f - s.z) >> 21;
            v[3] = __float_as_uint(1.0f - s.w) >> 21;
#pragma unroll
            for (int l = 0; l < 4; ++l) {
                unsigned grp = __match_any_sync(__activemask(), v[l]);
                int leader = __ffs(grp) - 1;
                if ((int)(threadIdx.x & 31) == leader)
                    atomicAdd(&hist[v[l]], (unsigned)__popc(grp));
            }
        }
    }
    __syncthreads();

    // ---- pivot scan (coarse 64 x 32, then fine) ----
    if (tid < 64) {
        unsigned s = 0;
#pragma unroll
        for (int i = 0; i < 32; ++i) s += hist[tid * 32 + i];
        coarse[tid] = s;
    }
    __syncthreads();
    if (tid == 0) {
        unsigned cum = 0;
        int seg = 0;
        while (cum + coarse[seg] < PRE) { cum += coarse[seg]; ++seg; }
        int p = seg * 32;
        while (cum + hist[p] < PRE) { cum += hist[p]; ++p; }
        sh_th1 = p; sh_D = (int)cum; sh_cnt = (int)(cum + hist[p]); sh_lvl = 1;
    }
    __syncthreads();

    // ---- refinement level 2: next 11 bits (rare) ----
    if (sh_cnt > 1024) {
        for (int i = tid; i < 2048; i += T) hist[i] = 0;
        __syncthreads();
        unsigned th1 = (unsigned)sh_th1;
        for (int a = tid; a < An; a += T) {
            unsigned t2 = __float_as_uint(1.0f - ms[a]);
            if ((t2 >> 21) == th1) atomicAdd(&hist[(t2 >> 10) & 0x7FF], 1u);
        }
        __syncthreads();
        if (tid < 64) {
            unsigned s = 0;
            for (int i = 0; i < 32; ++i) s += hist[tid * 32 + i];
            coarse[tid] = s;
        }
        __syncthreads();
        if (tid == 0) {
            unsigned target = PRE - (unsigned)sh_D;
            unsigned cum = 0; int seg = 0;
            while (cum + coarse[seg] < target) { cum += coarse[seg]; ++seg; }
            int p = seg * 32;
            while (cum + hist[p] < target) { cum += hist[p]; ++p; }
            sh_th2 = p; sh_D += (int)cum; sh_cnt = sh_D + (int)hist[p]; sh_lvl = 2;
        }
        __syncthreads();
    }

    // ---- refinement level 3: last 10 bits (essentially never) ----
    if (sh_cnt > 1024) {
        for (int i = tid; i < 2048; i += T) hist[i] = 0;
        __syncthreads();
        unsigned th1 = (unsigned)sh_th1, th2 = (unsigned)sh_th2;
        for (int a = tid; a < An; a += T) {
            unsigned t2 = __float_as_uint(1.0f - ms[a]);
            if ((t2 >> 21) == th1 && ((t2 >> 10) & 0x7FF) == th2)
                atomicAdd(&hist[t2 & 0x3FF], 1u);
        }
        __syncthreads();
        if (tid < 64) {
            unsigned s = 0;
            for (int i = 0; i < 32; ++i) s += hist[tid * 32 + i];
            coarse[tid] = s;
        }
        __syncthreads();
        if (tid == 0) {
            unsigned target = PRE - (unsigned)sh_D;
            unsigned cum = 0; int seg = 0;
            while (cum + coarse[seg] < target) { cum += coarse[seg]; ++seg; }
            int p = seg * 32;
            while (cum + hist[p] < target) { cum += hist[p]; ++p; }
            sh_th3 = p; sh_D += (int)cum; sh_cnt = sh_D + (int)hist[p]; sh_lvl = 3;
        }
        __syncthreads();
    }

    // ---- compaction of the superset with TRUE keys ----
    if (tid == 0) sh_pos = 0;
    __syncthreads();
    {
        unsigned th1 = (unsigned)sh_th1;
        unsigned th2 = (unsigned)sh_th2, th3 = (unsigned)sh_th3;
        int lvl = sh_lvl;
        for (int it = 0; it < QI; ++it) {
            int q = it * T + tid;
            if (q < QAn) {
                float4 s4 = ((const float4*)ms)[q];
                float sv[4] = {s4.x, s4.y, s4.z, s4.w};
#pragma unroll
                for (int l = 0; l < 4; ++l) {
                    unsigned t2 = __float_as_uint(1.0f - sv[l]);
                    unsigned b1 = t2 >> 21;
                    bool take;
                    if (b1 != th1) take = (b1 < th1);
                    else if (lvl == 1) take = true;
                    else {
                        unsigned b2 = (t2 >> 10) & 0x7FF;
                        if (b2 != th2) take = (b2 < th2);
                        else if (lvl == 2) take = true;
                        else take = ((t2 & 0x3FF) <= th3);
                    }
                    if (take) {
                        int pos = atomicAdd(&sh_pos, 1);
                        if (pos < 1024) {
                            int a = q * 4 + l;
                            keys[pos] = ((unsigned long long)__float_as_uint(sv[l]) << 32)
                                      | (unsigned)(~a);
                        }
                    }
                }
            }
        }
    }
    __syncthreads();
    int cnt = sh_pos;
    if (cnt > 1024) cnt = 1024;
    for (int i = cnt + tid; i < 1024; i += T) keys[i] = 0ULL;
    __syncthreads();

    // ---- hybrid bitonic sort, descending by true key ----
    {
        unsigned long long v = keys[tid];
        for (int k2 = 2; k2 <= 1024; k2 <<= 1) {
            bool dirmax = ((tid & k2) == 0);  // descending half
            for (int j = k2 >> 1; j >= 1; j >>= 1) {
                unsigned long long o;
                if (j >= 32) {
                    keys[tid] = v;
                    __syncthreads();
                    o = keys[tid ^ j];
                    __syncthreads();
                } else {
                    o = __shfl_xor_sync(0xFFFFFFFFu, v, j);
                }
                bool lower = ((tid & j) == 0);
                bool takeMax = (lower == dirmax);
                bool gt = (v > o);
                v = (takeMax == gt) ? v : o;
            }
        }
        keys[tid] = v;
        __syncthreads();
    }

    // ---- load boxes/classes for sorted top-750; max coordinate ----
    if (tid == 0) sh_maxbits = 0;
    __syncthreads();
    if (tid < PRE) {
        int i = tid;
        int a = (int)(~(unsigned)(keys[i] & 0xFFFFFFFFULL));
        const float* rb = raw + (size_t)b * 84 * An;
        float x1 = rb[0 * (size_t)An + a];
        float y1 = rb[1 * (size_t)An + a];
        float x2 = rb[2 * (size_t)An + a];
        float y2 = rb[3 * (size_t)An + a];
        bx1[i] = x1; by1[i] = y1; bx2[i] = x2; by2[i] = y2;
        bcls[i] = cl[a];
        float m = fmaxf(fmaxf(x1, y1), fmaxf(x2, y2));
        atomicMax(&sh_maxbits, __float_as_int(m));
        keep[i] = 1;
    }
    __syncthreads();

    float off_scale = __int_as_float(sh_maxbits) + 1.0f;
    if (tid < PRE) {
        int i = tid;
        float off = (float)bcls[i] * off_scale;
        float x1 = bx1[i] + off, y1 = by1[i] + off;
        float x2 = bx2[i] + off, y2 = by2[i] + off;
        bx1[i] = x1; by1[i] = y1; bx2[i] = x2; by2[i] = y2;
        barea[i] = (x2 - x1) * (y2 - y1);
    }
    __syncthreads();

    // ---- sequential NMS, skip suppressed rows sync-free, exit at 30 kept ----
    {
        int i = 0, kept = 0;
        while (i < PRE && kept < POST) {
            while (i < PRE && !keep[i]) ++i;   // keep[] stable here
            if (i >= PRE) break;
            float X1 = bx1[i], Y1 = by1[i], X2 = bx2[i], Y2 = by2[i], AR = barea[i];
            int CI = bcls[i];
            for (int j = i + 1 + tid; j < PRE; j += T) {
                if (keep[j] && bcls[j] == CI) {
                    float iw = fmaxf(fminf(X2, bx2[j]) - fmaxf(X1, bx1[j]), 0.0f);
                    float ih = fmaxf(fminf(Y2, by2[j]) - fmaxf(Y1, by1[j]), 0.0f);
                    float inter = iw * ih;
                    float iou = __fdiv_rn(inter, AR + barea[j] - inter);
                    if (iou > 0.4f) keep[j] = 0;
                }
            }
            ++kept;
            ++i;
            __syncthreads();
        }
    }

    // ---- stable-partition: first 30 kept, then unkept fill ----
    if (tid == 0) {
        int c2 = 0;
        for (int i = 0; i < PRE && c2 < POST; ++i)
            if (keep[i]) {
                g_final[b * POST + c2] = (int)(~(unsigned)(keys[i] & 0xFFFFFFFFULL));
                c2++;
            }
        for (int i = 0; i < PRE && c2 < POST; ++i)
            if (!keep[i]) {
                g_final[b * POST + c2] = (int)(~(unsigned)(keys[i] & 0xFFFFFFFFULL));
                c2++;
            }
    }
}

// ---------------------------------------------------------------------------
// K3: gather features/boxes/scores for the 480 final selections.
// ---------------------------------------------------------------------------
__global__ void k_gather(const float* __restrict__ raw,
                         const float* __restrict__ vid,
                         const float* __restrict__ reg,
                         float* __restrict__ out) {
    int r = blockIdx.x;
    int b = r / POST;
    int a = g_final[r];
    int t = threadIdx.x;

    size_t row = ((size_t)b * An + a) * CH;
    const float4* v = (const float4*)(vid + row);
    const float4* g = (const float4*)(reg + row);
    float4* oc = (float4*)(out + OUT_CLS_OFF + (size_t)r * CH);
    float4* og = (float4*)(out + OUT_REG_OFF + (size_t)r * CH);

    if (t < 64) oc[t] = __ldg(v + t);
    else        og[t - 64] = __ldg(g + (t - 64));

    if (t < 4)
        out[OUT_BOX_OFF + r * 4 + t] = raw[(size_t)b * 84 * An + (size_t)t * An + a];
    if (t == 4)
        out[OUT_SC_OFF + r] = g_maxs[(size_t)b * An + a];
}

// ---------------------------------------------------------------------------
extern "C" void kernel_launch(void* const* d_in, const int* in_sizes, int n_in,
                              void* d_out, int out_size) {
    const float* raw = (const float*)d_in[0];
    const float* vid = (const float*)d_in[1];
    const float* reg = (const float*)d_in[2];
    float* out = (float*)d_out;

    int threads1 = 256;
    int blocks1 = (Bn * QAn * 2 + threads1 - 1) / threads1;
    k_maxscore<<<blocks1, threads1>>>(raw);
    k_select<<<Bn, 1024>>>(raw);
    k_gather<<<Bn * POST, 128>>>(raw, vid, reg, out);
}

// round 3
// speedup vs baseline: 1.7175x; 1.0244x over previous
#include <cuda_runtime.h>
#include <cstdint>

#define Bn    16
#define NCn   80
#define An    33600
#define QAn   (An/4)          /* 8400 */
#define PRE   750
#define POST  30
#define CH    256

#define OUT_CLS_OFF  0
#define OUT_REG_OFF  (Bn*POST*CH)
#define OUT_BOX_OFF  (2*Bn*POST*CH)
#define OUT_SC_OFF   (2*Bn*POST*CH + Bn*POST*4)

__device__ float g_maxs[Bn * An];
__device__ int   g_cls[Bn * An];

// ---------------------------------------------------------------------------
// K1: per-anchor max+argmax over 80 classes (R1 proven form: 1 thread per
// 4 consecutive anchors, float4 loads, fully coalesced, 74% DRAM).
// ---------------------------------------------------------------------------
__global__ void k_maxscore(const float* __restrict__ raw) {
    int t = blockIdx.x * blockDim.x + threadIdx.x;
    if (t >= Bn * QAn) return;
    int b = t / QAn;
    int q = t - b * QAn;

    const float* base = raw + (size_t)b * 84 * An + (size_t)4 * An;

    float4 best = __ldg((const float4*)base + q);
    int4 bi = make_int4(0, 0, 0, 0);
#pragma unroll 4
    for (int c = 1; c < NCn; ++c) {
        float4 v = __ldg((const float4*)(base + (size_t)c * An) + q);
        if (v.x > best.x) { best.x = v.x; bi.x = c; }
        if (v.y > best.y) { best.y = v.y; bi.y = c; }
        if (v.z > best.z) { best.z = v.z; bi.z = c; }
        if (v.w > best.w) { best.w = v.w; bi.w = c; }
    }
    ((float4*)g_maxs)[t] = best;
    ((int4*)g_cls)[t] = bi;
}

// ---------------------------------------------------------------------------
// K2 (fused): per-frame top-750 select + sort + NMS + feature gather.
// ---------------------------------------------------------------------------
__global__ __launch_bounds__(1024) void k_select(const float* __restrict__ raw,
                                                 const float* __restrict__ vid,
                                                 const float* __restrict__ reg,
                                                 float* __restrict__ out) {
    const int b = blockIdx.x;
    const int tid = threadIdx.x;
    const int T = 1024;

    __shared__ unsigned hist[2048];
    __shared__ unsigned coarse[64];
    __shared__ unsigned long long keys[1024];
    __shared__ float bx1[PRE], by1[PRE], bx2[PRE], by2[PRE], barea[PRE];
    __shared__ int bcls[PRE];
    __shared__ int keep[PRE];
    __shared__ unsigned pairs[1024];
    __shared__ int sh_final[POST];
    __shared__ int sh_pos, sh_maxbits, sh_np, sh_kept, sh_fallback;
    __shared__ int sh_th1, sh_th2, sh_th3, sh_lvl, sh_D, sh_cnt;

    const float* ms = g_maxs + (size_t)b * An;
    const int* cl = g_cls + (size_t)b * An;

    // ---- level-1 histogram: top 11 bits of bits(1-s) (order-reversing) ----
    for (int i = tid; i < 2048; i += T) hist[i] = 0;
    __syncthreads();

    const int QI = (QAn + T - 1) / T;  // 9
    for (int it = 0; it < QI; ++it) {
        int q = it * T + tid;
        if (q < QAn) {
            float4 s = ((const float4*)ms)[q];
            unsigned v[4];
            v[0] = __float_as_uint(1.0f - s.x) >> 21;
            v[1] = __float_as_uint(1.0f - s.y) >> 21;
            v[2] = __float_as_uint(1.0f - s.z) >> 21;
            v[3] = __float_as_uint(1.0f - s.w) >> 21;
#pragma unroll
            for (int l = 0; l < 4; ++l) {
                unsigned grp = __match_any_sync(__activemask(), v[l]);
                int leader = __ffs(grp) - 1;
                if ((int)(threadIdx.x & 31) == leader)
                    atomicAdd(&hist[v[l]], (unsigned)__popc(grp));
            }
        }
    }
    __syncthreads();

    // ---- pivot scan ----
    if (tid < 64) {
        unsigned s = 0;
#pragma unroll
        for (int i = 0; i < 32; ++i) s += hist[tid * 32 + i];
        coarse[tid] = s;
    }
    __syncthreads();
    if (tid == 0) {
        unsigned cum = 0; int seg = 0;
        while (cum + coarse[seg] < PRE) { cum += coarse[seg]; ++seg; }
        int p = seg * 32;
        while (cum + hist[p] < PRE) { cum += hist[p]; ++p; }
        sh_th1 = p; sh_D = (int)cum; sh_cnt = (int)(cum + hist[p]); sh_lvl = 1;
    }
    __syncthreads();

    // ---- refinement level 2 (rare) ----
    if (sh_cnt > 1024) {
        for (int i = tid; i < 2048; i += T) hist[i] = 0;
        __syncthreads();
        unsigned th1 = (unsigned)sh_th1;
        for (int a = tid; a < An; a += T) {
            unsigned t2 = __float_as_uint(1.0f - ms[a]);
            if ((t2 >> 21) == th1) atomicAdd(&hist[(t2 >> 10) & 0x7FF], 1u);
        }
        __syncthreads();
        if (tid < 64) {
            unsigned s = 0;
            for (int i = 0; i < 32; ++i) s += hist[tid * 32 + i];
            coarse[tid] = s;
        }
        __syncthreads();
        if (tid == 0) {
            unsigned target = PRE - (unsigned)sh_D;
            unsigned cum = 0; int seg = 0;
            while (cum + coarse[seg] < target) { cum += coarse[seg]; ++seg; }
            int p = seg * 32;
            while (cum + hist[p] < target) { cum += hist[p]; ++p; }
            sh_th2 = p; sh_D += (int)cum; sh_cnt = sh_D + (int)hist[p]; sh_lvl = 2;
        }
        __syncthreads();
    }

    // ---- refinement level 3 (essentially never) ----
    if (sh_cnt > 1024) {
        for (int i = tid; i < 2048; i += T) hist[i] = 0;
        __syncthreads();
        unsigned th1 = (unsigned)sh_th1, th2 = (unsigned)sh_th2;
        for (int a = tid; a < An; a += T) {
            unsigned t2 = __float_as_uint(1.0f - ms[a]);
            if ((t2 >> 21) == th1 && ((t2 >> 10) & 0x7FF) == th2)
                atomicAdd(&hist[t2 & 0x3FF], 1u);
        }
        __syncthreads();
        if (tid < 64) {
            unsigned s = 0;
            for (int i = 0; i < 32; ++i) s += hist[tid * 32 + i];
            coarse[tid] = s;
        }
        __syncthreads();
        if (tid == 0) {
            unsigned target = PRE - (unsigned)sh_D;
            unsigned cum = 0; int seg = 0;
            while (cum + coarse[seg] < target) { cum += coarse[seg]; ++seg; }
            int p = seg * 32;
            while (cum + hist[p] < target) { cum += hist[p]; ++p; }
            sh_th3 = p; sh_D += (int)cum; sh_cnt = sh_D + (int)hist[p]; sh_lvl = 3;
        }
        __syncthreads();
    }

    // ---- compaction of superset with TRUE keys (score_bits<<32 | ~index) ----
    if (tid == 0) sh_pos = 0;
    __syncthreads();
    {
        unsigned th1 = (unsigned)sh_th1;
        unsigned th2 = (unsigned)sh_th2, th3 = (unsigned)sh_th3;
        int lvl = sh_lvl;
        for (int it = 0; it < QI; ++it) {
            int q = it * T + tid;
            if (q < QAn) {
                float4 s4 = ((const float4*)ms)[q];
                float sv[4] = {s4.x, s4.y, s4.z, s4.w};
#pragma unroll
                for (int l = 0; l < 4; ++l) {
                    unsigned t2 = __float_as_uint(1.0f - sv[l]);
                    unsigned b1 = t2 >> 21;
                    bool take;
                    if (b1 != th1) take = (b1 < th1);
                    else if (lvl == 1) take = true;
                    else {
                        unsigned b2 = (t2 >> 10) & 0x7FF;
                        if (b2 != th2) take = (b2 < th2);
                        else if (lvl == 2) take = true;
                        else take = ((t2 & 0x3FF) <= th3);
                    }
                    if (take) {
                        int pos = atomicAdd(&sh_pos, 1);
                        if (pos < 1024) {
                            int a = q * 4 + l;
                            keys[pos] = ((unsigned long long)__float_as_uint(sv[l]) << 32)
                                      | (unsigned)(~a);
                        }
                    }
                }
            }
        }
    }
    __syncthreads();
    int cnt = sh_pos;
    if (cnt > 1024) cnt = 1024;
    for (int i = cnt + tid; i < 1024; i += T) keys[i] = 0ULL;
    __syncthreads();

    // ---- hybrid bitonic sort, descending by true key ----
    {
        unsigned long long v = keys[tid];
        for (int k2 = 2; k2 <= 1024; k2 <<= 1) {
            bool dirmax = ((tid & k2) == 0);
            for (int j = k2 >> 1; j >= 1; j >>= 1) {
                unsigned long long o;
                if (j >= 32) {
                    keys[tid] = v;
                    __syncthreads();
                    o = keys[tid ^ j];
                    __syncthreads();
                } else {
                    o = __shfl_xor_sync(0xFFFFFFFFu, v, j);
                }
                bool lower = ((tid & j) == 0);
                bool takeMax = (lower == dirmax);
                bool gt = (v > o);
                v = (takeMax == gt) ? v : o;
            }
        }
        keys[tid] = v;
        __syncthreads();
    }

    // ---- load boxes/classes for the sorted top-750; max coord ----
    if (tid == 0) { sh_maxbits = 0; sh_fallback = 0; }
    __syncthreads();
    if (tid < PRE) {
        int i = tid;
        int a = (int)(~(unsigned)(keys[i] & 0xFFFFFFFFULL));
        const float* rb = raw + (size_t)b * 84 * An;
        float x1 = rb[0 * (size_t)An + a];
        float y1 = rb[1 * (size_t)An + a];
        float x2 = rb[2 * (size_t)An + a];
        float y2 = rb[3 * (size_t)An + a];
        bx1[i] = x1; by1[i] = y1; bx2[i] = x2; by2[i] = y2;
        bcls[i] = cl[a];
        float m = fmaxf(fmaxf(x1, y1), fmaxf(x2, y2));
        atomicMax(&sh_maxbits, __float_as_int(m));
    }
    __syncthreads();

    float off_scale = __int_as_float(sh_maxbits) + 1.0f;
    if (tid < PRE) {
        int i = tid;
        float off = (float)bcls[i] * off_scale;
        float x1 = bx1[i] + off, y1 = by1[i] + off;
        float x2 = bx2[i] + off, y2 = by2[i] + off;
        bx1[i] = x1; by1[i] = y1; bx2[i] = x2; by2[i] = y2;
        barea[i] = (x2 - x1) * (y2 - y1);
    }
    __syncthreads();

    // ---- NMS: windowed conflict pairs + serial resolve ----
    {
        int W = 64;
        for (;;) {
            if (tid == 0) sh_np = 0;
            if (tid < PRE) keep[tid] = 1;
            __syncthreads();

            for (int p = tid; p < W * PRE; p += T) {
                int i = p / PRE;
                int j = p - i * PRE;
                if (j > i && bcls[i] == bcls[j]) {
                    float iw = fmaxf(fminf(bx2[i], bx2[j]) - fmaxf(bx1[i], bx1[j]), 0.0f);
                    float ih = fmaxf(fminf(by2[i], by2[j]) - fmaxf(by1[i], by1[j]), 0.0f);
                    float inter = iw * ih;
                    float iou = __fdiv_rn(inter, barea[i] + barea[j] - inter);
                    if (iou > 0.4f) {
                        int k = atomicAdd(&sh_np, 1);
                        if (k < 1024) pairs[k] = ((unsigned)i << 10) | (unsigned)j;
                    }
                }
            }
            __syncthreads();
            int np = sh_np;
            if (np > 1024) { if (tid == 0) sh_fallback = 1; __syncthreads(); break; }

            if (tid == 0) {
                // insertion sort by (i,j) ascending
                for (int a2 = 1; a2 < np; ++a2) {
                    unsigned v = pairs[a2];
                    int b2 = a2 - 1;
                    while (b2 >= 0 && pairs[b2] > v) { pairs[b2 + 1] = pairs[b2]; --b2; }
                    pairs[b2 + 1] = v;
                }
                // exact sequential suppression semantics
                for (int p2 = 0; p2 < np; ++p2) {
                    unsigned v = pairs[p2];
                    int i = (int)(v >> 10), j = (int)(v & 1023u);
                    if (keep[i]) keep[j] = 0;
                }
                int kept = 0;
                for (int i = 0; i < W && kept < POST; ++i) kept += keep[i];
                sh_kept = kept;
            }
            __syncthreads();
            if (sh_kept >= POST || W >= PRE) break;
            W = (W * 4 < PRE) ? W * 4 : PRE;
            __syncthreads();
        }
    }

    // ---- fallback (pathological conflict counts only): barrier-iterative ----
    if (sh_fallback) {
        if (tid < PRE) keep[tid] = 1;
        __syncthreads();
        int i = 0, kept = 0;
        while (i < PRE && kept < POST) {
            while (i < PRE && !keep[i]) ++i;
            if (i >= PRE) break;
            float X1 = bx1[i], Y1 = by1[i], X2 = bx2[i], Y2 = by2[i], AR = barea[i];
            int CI = bcls[i];
            for (int j = i + 1 + tid; j < PRE; j += T) {
                if (keep[j] && bcls[j] == CI) {
                    float iw = fmaxf(fminf(X2, bx2[j]) - fmaxf(X1, bx1[j]), 0.0f);
                    float ih = fmaxf(fminf(Y2, by2[j]) - fmaxf(Y1, by1[j]), 0.0f);
                    float inter = iw * ih;
                    float iou = __fdiv_rn(inter, AR + barea[j] - inter);
                    if (iou > 0.4f) keep[j] = 0;
                }
            }
            ++kept; ++i;
            __syncthreads();
        }
    }

    // ---- stable-partition: first 30 kept, then unkept fill ----
    if (tid == 0) {
        int c2 = 0;
        for (int i = 0; i < PRE && c2 < POST; ++i)
            if (keep[i]) sh_final[c2++] = i;
        for (int i = 0; i < PRE && c2 < POST; ++i)
            if (!keep[i]) sh_final[c2++] = i;
    }
    __syncthreads();

    // ---- fused gather: features, boxes, scores for this frame's 30 rows ----
    for (int w2 = tid; w2 < POST * 128; w2 += T) {
        int c = w2 >> 7;
        int f = w2 & 127;
        int i = sh_final[c];
        int a = (int)(~(unsigned)(keys[i] & 0xFFFFFFFFULL));
        size_t r = (size_t)b * POST + c;
        size_t row = ((size_t)b * An + a) * CH;
        if (f < 64)
            ((float4*)(out + OUT_CLS_OFF))[r * 64 + f] = __ldg((const float4*)(vid + row) + f);
        else
            ((float4*)(out + OUT_REG_OFF))[r * 64 + (f - 64)] = __ldg((const float4*)(reg + row) + (f - 64));
    }
    if (tid < POST * 4) {
        int c = tid >> 2, d = tid & 3;
        int i = sh_final[c];
        int a = (int)(~(unsigned)(keys[i] & 0xFFFFFFFFULL));
        out[OUT_BOX_OFF + (b * POST + c) * 4 + d] = raw[(size_t)b * 84 * An + (size_t)d * An + a];
    }
    if (tid >= 128 && tid < 128 + POST) {
        int c = tid - 128;
        int i = sh_final[c];
        out[OUT_SC_OFF + b * POST + c] = __uint_as_float((unsigned)(keys[i] >> 32));
    }
}

// ---------------------------------------------------------------------------
extern "C" void kernel_launch(void* const* d_in, const int* in_sizes, int n_in,
                              void* d_out, int out_size) {
    const float* raw = (const float*)d_in[0];
    const float* vid = (const float*)d_in[1];
    const float* reg = (const float*)d_in[2];
    float* out = (float*)d_out;

    int threads1 = 256;
    int blocks1 = (Bn * QAn + threads1 - 1) / threads1;
    k_maxscore<<<blocks1, threads1>>>(raw);
    k_select<<<Bn, 1024>>>(raw, vid, reg, out);
}

// round 4
// speedup vs baseline: 1.7336x; 1.0094x over previous
#include <cuda_runtime.h>
#include <cstdint>

#define Bn    16
#define NCn   80
#define An    33600
#define QAn   (An/4)          /* 8400 */
#define PRE   750
#define POST  30
#define CH    256
#define HB    16384           /* histogram bins per frame (bits(1-s)>>16 <= 0x3F80) */
#define CAP   1024            /* candidate capacity per frame */

#define OUT_CLS_OFF  0
#define OUT_REG_OFF  (Bn*POST*CH)
#define OUT_BOX_OFF  (2*Bn*POST*CH)
#define OUT_SC_OFF   (2*Bn*POST*CH + Bn*POST*4)

__device__ float              g_maxs[Bn * An];
__device__ int                g_cls[Bn * An];
__device__ unsigned           g_hist[Bn * HB];     // zero-init at load; re-zeroed by k_pivot
__device__ unsigned long long g_cand[Bn * CAP];
__device__ int                g_cnt[Bn];
__device__ int                g_thresh[Bn];

static __device__ __forceinline__ unsigned score_bin(float s) {
    return __float_as_uint(1.0f - s) >> 16;   // monotone: bin ascending <=> score descending
}

// ---------------------------------------------------------------------------
// K1: per-anchor max+argmax over 80 classes (proven R1 form) + global
// histogram of the max score (4 atomics per thread, at loop end).
// ---------------------------------------------------------------------------
__global__ void k_maxscore(const float* __restrict__ raw) {
    int t = blockIdx.x * blockDim.x + threadIdx.x;
    if (t >= Bn * QAn) return;
    int b = t / QAn;

    const float* base = raw + (size_t)b * 84 * An + (size_t)4 * An;
    int q = t - b * QAn;

    float4 best = __ldg((const float4*)base + q);
    int4 bi = make_int4(0, 0, 0, 0);
#pragma unroll 4
    for (int c = 1; c < NCn; ++c) {
        float4 v = __ldg((const float4*)(base + (size_t)c * An) + q);
        if (v.x > best.x) { best.x = v.x; bi.x = c; }
        if (v.y > best.y) { best.y = v.y; bi.y = c; }
        if (v.z > best.z) { best.z = v.z; bi.z = c; }
        if (v.w > best.w) { best.w = v.w; bi.w = c; }
    }
    ((float4*)g_maxs)[t] = best;
    ((int4*)g_cls)[t] = bi;

    unsigned* H = g_hist + (size_t)b * HB;
    atomicAdd(&H[score_bin(best.x)], 1u);
    atomicAdd(&H[score_bin(best.y)], 1u);
    atomicAdd(&H[score_bin(best.z)], 1u);
    atomicAdd(&H[score_bin(best.w)], 1u);
}

// ---------------------------------------------------------------------------
// K2: per-frame pivot bin from the 16384-bin histogram (block scan), then
// zero the histogram chunk-by-chunk (ready for next replay) and reset g_cnt.
// ---------------------------------------------------------------------------
__global__ __launch_bounds__(1024) void k_pivot() {
    const int b = blockIdx.x;
    const int tid = threadIdx.x;
    unsigned* H = g_hist + (size_t)b * HB;

    const int CHK = HB / 1024;  // 16 bins per thread
    int base = tid * CHK;

    unsigned s = 0;
#pragma unroll
    for (int i = 0; i < CHK / 4; ++i) {
        uint4 v = ((uint4*)(H + base))[i];
        s += v.x + v.y + v.z + v.w;
    }

    // block exclusive scan of s
    unsigned lane = tid & 31, wid = tid >> 5;
    unsigned v = s;
#pragma unroll
    for (int o = 1; o < 32; o <<= 1) {
        unsigned n = __shfl_up_sync(0xFFFFFFFFu, v, o);
        if (lane >= o) v += n;
    }
    __shared__ unsigned wsum[32];
    if (lane == 31) wsum[wid] = v;
    __syncthreads();
    if (wid == 0) {
        unsigned w = wsum[lane];
#pragma unroll
        for (int o = 1; o < 32; o <<= 1) {
            unsigned n = __shfl_up_sync(0xFFFFFFFFu, w, o);
            if (lane >= o) w += n;
        }
        wsum[lane] = w;
    }
    __syncthreads();
    unsigned incl = v + (wid ? wsum[wid - 1] : 0u);
    unsigned excl = incl - s;

    if (excl < PRE && incl >= PRE) {
        unsigned c = excl;
        int p = base;
        while (c + H[p] < PRE) { c += H[p]; ++p; }
        g_thresh[b] = p;
        g_cnt[b] = 0;
    }

    // zero own chunk (walk above only touches own chunk; program order suffices)
#pragma unroll
    for (int i = 0; i < CHK / 4; ++i)
        ((uint4*)(H + base))[i] = make_uint4(0, 0, 0, 0);
}

// ---------------------------------------------------------------------------
// K3: chip-wide compaction — push true keys (score_bits<<32 | ~anchor) of all
// anchors with bin <= t* into per-frame candidate buffers.
// ---------------------------------------------------------------------------
__global__ void k_compact() {
    int t = blockIdx.x * blockDim.x + threadIdx.x;
    if (t >= Bn * QAn) return;
    int b = t / QAn;
    int q = t - b * QAn;

    unsigned th = (unsigned)g_thresh[b];
    float4 s4 = ((const float4*)g_maxs)[t];
    float sv[4] = {s4.x, s4.y, s4.z, s4.w};
#pragma unroll
    for (int l = 0; l < 4; ++l) {
        if (score_bin(sv[l]) <= th) {
            int pos = atomicAdd(&g_cnt[b], 1);
            if (pos < CAP) {
                int a = q * 4 + l;
                g_cand[b * CAP + pos] =
                    ((unsigned long long)__float_as_uint(sv[l]) << 32) | (unsigned)(~a);
            }
        }
    }
}

// ---------------------------------------------------------------------------
// K4: per-frame — sort candidates (exact top-750 order), NMS, fused gather.
// ---------------------------------------------------------------------------
__global__ __launch_bounds__(1024) void k_select(const float* __restrict__ raw,
                                                 const float* __restrict__ vid,
                                                 const float* __restrict__ reg,
                                                 float* __restrict__ out) {
    const int b = blockIdx.x;
    const int tid = threadIdx.x;
    const int T = 1024;

    __shared__ unsigned long long keys[1024];
    __shared__ float bx1[PRE], by1[PRE], bx2[PRE], by2[PRE], barea[PRE];
    __shared__ int bcls[PRE];
    __shared__ int keep[PRE];
    __shared__ unsigned pairs[1024];
    __shared__ int sh_final[POST];
    __shared__ unsigned hist[256];
    __shared__ unsigned long long sh_prefix;
    __shared__ unsigned sh_k;
    __shared__ int sh_pos, sh_maxbits, sh_np, sh_kept, sh_fallback;

    const float* ms = g_maxs + (size_t)b * An;
    const int* cl = g_cls + (size_t)b * An;

    int cnt = g_cnt[b];

    if (cnt <= CAP) {
        // fast path: load candidates coalesced, pad
        keys[tid] = (tid < cnt) ? g_cand[b * CAP + tid] : 0ULL;
    } else {
        // exact fallback (provably ~never): 8-pass 64-bit radix select over ms
        unsigned long long prefix = 0ULL;
        unsigned kk = PRE;
        const int ITER = (An + T - 1) / T;
        for (int pass = 0; pass < 8; ++pass) {
            int shift = 56 - pass * 8;
            unsigned long long hi_mask = (pass == 0) ? 0ULL : (~0ULL << (unsigned)(shift + 8));
            for (int i = tid; i < 256; i += T) hist[i] = 0;
            __syncthreads();
            for (int it = 0; it < ITER; ++it) {
                int a = it * T + tid;
                if (a < An) {
                    unsigned long long key =
                        ((unsigned long long)__float_as_uint(ms[a]) << 32) | (unsigned)(~a);
                    if ((key & hi_mask) == prefix)
                        atomicAdd(&hist[(unsigned)(key >> shift) & 255u], 1u);
                }
            }
            __syncthreads();
            if (tid == 0) {
                unsigned cum = 0; int d = 255;
                for (; d >= 0; --d) {
                    unsigned c = hist[d];
                    if (cum + c >= kk) break;
                    cum += c;
                }
                if (d < 0) d = 0;
                prefix |= ((unsigned long long)d) << shift;
                kk -= cum;
                sh_prefix = prefix; sh_k = kk;
            }
            __syncthreads();
            prefix = sh_prefix; kk = sh_k;
            __syncthreads();
        }
        if (tid == 0) sh_pos = 0;
        __syncthreads();
        for (int a = tid; a < An; a += T) {
            unsigned long long key =
                ((unsigned long long)__float_as_uint(ms[a]) << 32) | (unsigned)(~a);
            if (key >= prefix) {
                int pos = atomicAdd(&sh_pos, 1);
                if (pos < 1024) keys[pos] = key;
            }
        }
        __syncthreads();
        int c2 = sh_pos; if (c2 > 1024) c2 = 1024;
        for (int i = c2 + tid; i < 1024; i += T) keys[i] = 0ULL;
    }
    __syncthreads();

    // ---- hybrid bitonic sort, descending by true key ----
    {
        unsigned long long v = keys[tid];
        for (int k2 = 2; k2 <= 1024; k2 <<= 1) {
            bool dirmax = ((tid & k2) == 0);
            for (int j = k2 >> 1; j >= 1; j >>= 1) {
                unsigned long long o;
                if (j >= 32) {
                    keys[tid] = v;
                    __syncthreads();
                    o = keys[tid ^ j];
                    __syncthreads();
                } else {
                    o = __shfl_xor_sync(0xFFFFFFFFu, v, j);
                }
                bool lower = ((tid & j) == 0);
                bool takeMax = (lower == dirmax);
                bool gt = (v > o);
                v = (takeMax == gt) ? v : o;
            }
        }
        keys[tid] = v;
        __syncthreads();
    }

    // ---- load boxes/classes for sorted top-750; max coordinate ----
    if (tid == 0) { sh_maxbits = 0; sh_fallback = 0; }
    __syncthreads();
    if (tid < PRE) {
        int i = tid;
        int a = (int)(~(unsigned)(keys[i] & 0xFFFFFFFFULL));
        const float* rb = raw + (size_t)b * 84 * An;
        float x1 = rb[0 * (size_t)An + a];
        float y1 = rb[1 * (size_t)An + a];
        float x2 = rb[2 * (size_t)An + a];
        float y2 = rb[3 * (size_t)An + a];
        bx1[i] = x1; by1[i] = y1; bx2[i] = x2; by2[i] = y2;
        bcls[i] = cl[a];
        float m = fmaxf(fmaxf(x1, y1), fmaxf(x2, y2));
        atomicMax(&sh_maxbits, __float_as_int(m));
    }
    __syncthreads();

    float off_scale = __int_as_float(sh_maxbits) + 1.0f;
    if (tid < PRE) {
        int i = tid;
        float off = (float)bcls[i] * off_scale;
        float x1 = bx1[i] + off, y1 = by1[i] + off;
        float x2 = bx2[i] + off, y2 = by2[i] + off;
        bx1[i] = x1; by1[i] = y1; bx2[i] = x2; by2[i] = y2;
        barea[i] = (x2 - x1) * (y2 - y1);
    }
    __syncthreads();

    // ---- NMS: windowed conflict pairs + serial resolve ----
    {
        int W = 64;
        for (;;) {
            if (tid == 0) sh_np = 0;
            if (tid < PRE) keep[tid] = 1;
            __syncthreads();

            for (int p = tid; p < W * PRE; p += T) {
                int i = p / PRE;
                int j = p - i * PRE;
                if (j > i && bcls[i] == bcls[j]) {
                    float iw = fmaxf(fminf(bx2[i], bx2[j]) - fmaxf(bx1[i], bx1[j]), 0.0f);
                    float ih = fmaxf(fminf(by2[i], by2[j]) - fmaxf(by1[i], by1[j]), 0.0f);
                    float inter = iw * ih;
                    float iou = __fdiv_rn(inter, barea[i] + barea[j] - inter);
                    if (iou > 0.4f) {
                        int k = atomicAdd(&sh_np, 1);
                        if (k < 1024) pairs[k] = ((unsigned)i << 10) | (unsigned)j;
                    }
                }
            }
            __syncthreads();
            int np = sh_np;
            if (np > 1024) { if (tid == 0) sh_fallback = 1; __syncthreads(); break; }

            if (tid == 0) {
                for (int a2 = 1; a2 < np; ++a2) {
                    unsigned v = pairs[a2];
                    int b2 = a2 - 1;
                    while (b2 >= 0 && pairs[b2] > v) { pairs[b2 + 1] = pairs[b2]; --b2; }
                    pairs[b2 + 1] = v;
                }
                for (int p2 = 0; p2 < np; ++p2) {
                    unsigned v = pairs[p2];
                    int i = (int)(v >> 10), j = (int)(v & 1023u);
                    if (keep[i]) keep[j] = 0;
                }
                int kept = 0;
                for (int i = 0; i < W && kept < POST; ++i) kept += keep[i];
                sh_kept = kept;
            }
            __syncthreads();
            if (sh_kept >= POST || W >= PRE) break;
            W = (W * 4 < PRE) ? W * 4 : PRE;
            __syncthreads();
        }
    }

    if (sh_fallback) {  // pathological conflict counts only
        if (tid < PRE) keep[tid] = 1;
        __syncthreads();
        int i = 0, kept = 0;
        while (i < PRE && kept < POST) {
            while (i < PRE && !keep[i]) ++i;
            if (i >= PRE) break;
            float X1 = bx1[i], Y1 = by1[i], X2 = bx2[i], Y2 = by2[i], AR = barea[i];
            int CI = bcls[i];
            for (int j = i + 1 + tid; j < PRE; j += T) {
                if (keep[j] && bcls[j] == CI) {
                    float iw = fmaxf(fminf(X2, bx2[j]) - fmaxf(X1, bx1[j]), 0.0f);
                    float ih = fmaxf(fminf(Y2, by2[j]) - fmaxf(Y1, by1[j]), 0.0f);
                    float inter = iw * ih;
                    float iou = __fdiv_rn(inter, AR + barea[j] - inter);
                    if (iou > 0.4f) keep[j] = 0;
                }
            }
            ++kept; ++i;
            __syncthreads();
        }
    }

    // ---- stable-partition: first 30 kept, then unkept fill ----
    if (tid == 0) {
        int c2 = 0;
        for (int i = 0; i < PRE && c2 < POST; ++i)
            if (keep[i]) sh_final[c2++] = i;
        for (int i = 0; i < PRE && c2 < POST; ++i)
            if (!keep[i]) sh_final[c2++] = i;
    }
    __syncthreads();

    // ---- fused gather ----
    for (int w2 = tid; w2 < POST * 128; w2 += T) {
        int c = w2 >> 7;
        int f = w2 & 127;
        int i = sh_final[c];
        int a = (int)(~(unsigned)(keys[i] & 0xFFFFFFFFULL));
        size_t r = (size_t)b * POST + c;
        size_t row = ((size_t)b * An + a) * CH;
        if (f < 64)
            ((float4*)(out + OUT_CLS_OFF))[r * 64 + f] = __ldg((const float4*)(vid + row) + f);
        else
            ((float4*)(out + OUT_REG_OFF))[r * 64 + (f - 64)] = __ldg((const float4*)(reg + row) + (f - 64));
    }
    if (tid < POST * 4) {
        int c = tid >> 2, d = tid & 3;
        int i = sh_final[c];
        int a = (int)(~(unsigned)(keys[i] & 0xFFFFFFFFULL));
        out[OUT_BOX_OFF + (b * POST + c) * 4 + d] = raw[(size_t)b * 84 * An + (size_t)d * An + a];
    }
    if (tid >= 128 && tid < 128 + POST) {
        int c = tid - 128;
        int i = sh_final[c];
        out[OUT_SC_OFF + b * POST + c] = __uint_as_float((unsigned)(keys[i] >> 32));
    }
}

// ---------------------------------------------------------------------------
extern "C" void kernel_launch(void* const* d_in, const int* in_sizes, int n_in,
                              void* d_out, int out_size) {
    const float* raw = (const float*)d_in[0];
    const float* vid = (const float*)d_in[1];
    const float* reg = (const float*)d_in[2];
    float* out = (float*)d_out;

    int threads1 = 256;
    int blocks1 = (Bn * QAn + threads1 - 1) / threads1;
    k_maxscore<<<blocks1, threads1>>>(raw);
    k_pivot<<<Bn, 1024>>>();
    k_compact<<<blocks1, threads1>>>();
    k_select<<<Bn, 1024>>>(raw, vid, reg, out);
}